// round 11
// baseline (speedup 1.0000x reference)
#include <cuda_runtime.h>
#include <cuda_fp16.h>
#include <cstdint>
#include <math.h>

#define NROWS 16384
#define DDIM  64
#define BM    128
#define BN    64
#define NTILES   (NROWS / BN)     // 256
#define CHUNK    16               // tiles per task
#define NCHUNKS  (NTILES / CHUNK) // 16 chunks per rowblock
#define NTASKS   ((NROWS / BM) * NCHUNKS)   // 2048
#define GRID_P   444
#define NTHR  256
#define SCALE_A 28.853900817779268f   // log2(e)/tau
#define LN2F    0.6931471805599453f
#define BIAS_H2 0xCA00CA00u           // packed half2(-12, -12)
#define SMEM_A  24576                 // A stage / reduction overlay

__device__ __half g_ah[NROWS * DDIM];      // z1n * log2(e)/tau  [m][k]
__device__ __half g_bh[NROWS * DDIM];      // z2n               [n][k]
__device__ float  g_rowsum[NCHUNKS * NROWS];   // biased by 2^-12 (cancels)
__device__ float  g_pos[NROWS];                // biased logit (cancels)
__device__ float  g_part1[64];
__device__ unsigned g_task = 0;            // dynamic ticket (reset by normalize)
__device__ unsigned g_fin  = 0;            // finalize last-block counter

__device__ __forceinline__ uint32_t smem_u32(const void* p) {
    uint32_t a;
    asm("{ .reg .u64 t; cvta.to.shared.u64 t, %1; cvt.u32.u64 %0, t; }" : "=r"(a) : "l"(p));
    return a;
}
__device__ __forceinline__ uint32_t ex2_h2(uint32_t x) {
    uint32_t r; asm("ex2.approx.f16x2 %0, %1;" : "=r"(r) : "r"(x)); return r;
}
__device__ __forceinline__ uint32_t hadd2u(uint32_t a, uint32_t b) {
    uint32_t r; asm("add.rn.f16x2 %0, %1, %2;" : "=r"(r) : "r"(a), "r"(b)); return r;
}
__device__ __forceinline__ float2 h2f(uint32_t u) {
    __half2 h = *reinterpret_cast<__half2*>(&u);
    return __half22float2(h);
}
#define LDSM_X4(r0, r1, r2, r3, addr) \
    asm volatile("ldmatrix.sync.aligned.m8n8.x4.shared.b16 {%0,%1,%2,%3}, [%4];" \
        : "=r"(r0), "=r"(r1), "=r"(r2), "=r"(r3) : "r"(addr))
#define MMA16816_F16(d, a, b) \
    asm volatile("mma.sync.aligned.m16n8k16.row.col.f16.f16.f16.f16 " \
        "{%0,%1}, {%2,%3,%4,%5}, {%6,%7}, {%0,%1};" \
        : "+r"((d)[0]), "+r"((d)[1]) \
        : "r"((a)[0]), "r"((a)[1]), "r"((a)[2]), "r"((a)[3]), "r"((b)[0]), "r"((b)[1]))
#define CP_ASYNC16(dst, src) \
    asm volatile("cp.async.cg.shared.global [%0], [%1], 16;" :: "r"(dst), "l"(src))
#define CP_COMMIT()  asm volatile("cp.async.commit_group;" ::: "memory")
#define CP_WAIT(n)   asm volatile("cp.async.wait_group %0;" :: "n"(n) : "memory")

// ─────────────── Kernel 1: L2-normalize + fp16 quantize + scale fold ────────
__global__ void normalize_kernel(const float* __restrict__ z1,
                                 const float* __restrict__ z2) {
    if (blockIdx.x == 0 && threadIdx.x == 0) g_task = 0;   // reset ticket

    int warp = blockIdx.x * (blockDim.x >> 5) + (threadIdx.x >> 5);
    int lane = threadIdx.x & 31;
    int row  = warp * 2 + (lane >> 4);
    int l16  = lane & 15;

    const float* src; __half* dst; float scale; int r;
    if (row < NROWS) { src = z1; dst = g_ah; r = row;          scale = SCALE_A; }
    else             { src = z2; dst = g_bh; r = row - NROWS;  scale = 1.0f;    }

    float4 v = ((const float4*)(src + (size_t)r * DDIM))[l16];
    float ss = v.x * v.x + v.y * v.y + v.z * v.z + v.w * v.w;
    #pragma unroll
    for (int off = 8; off; off >>= 1)
        ss += __shfl_xor_sync(0xffffffffu, ss, off);
    float inv = scale / fmaxf(sqrtf(ss), 1e-12f);
    __half2 h0 = __floats2half2_rn(v.x * inv, v.y * inv);
    __half2 h1 = __floats2half2_rn(v.z * inv, v.w * inv);
    uint2 o = make_uint2(*(uint32_t*)&h0, *(uint32_t*)&h1);
    ((uint2*)(dst + (size_t)r * DDIM))[l16] = o;
}

// ── Kernel 2: persistent fp16 GEMM, 3-stage cp.async pipeline, 3 CTAs/SM ───
// smem: B buf0 [0,8K), buf1 [8K,16K), buf2 [16K,24K), A stage [24K,40K)
__global__ void __launch_bounds__(NTHR, 3) gemm_lse_kernel() {
    __shared__ __align__(128) char smem[40960];
    __shared__ int s_task;
    const uint32_t sb = smem_u32(smem);
    const int tid = threadIdx.x, lane = tid & 31, w = tid >> 5;
    const int wm = w >> 1, wn = w & 1;          // 4x2 warp grid, 32x32 tiles
    const int g = lane >> 3, r8 = lane & 7;
    const int kg = g & 1;
    const int q = lane >> 2, p4 = lane & 3;

    uint32_t brow[2]; int bnlo[2];
    #pragma unroll
    for (int p = 0; p < 2; p++) {
        int n = wn * 32 + p * 16 + (g >> 1) * 8 + r8;
        brow[p] = (uint32_t)(n * 128);
        bnlo[p] = n & 7;
    }

    for (;;) {
        if (tid == 0) s_task = (int)atomicAdd(&g_task, 1u);
        __syncthreads();
        const int task = s_task;
        if (task >= NTASKS) break;
        const int rb = task >> 4, ck = task & 15, t0 = ck << 4;

        // Preamble: group0 = A + B(t0), group1 = B(t0+1)
        {
            const uint4* asrc = (const uint4*)(g_ah + (size_t)rb * BM * DDIM);
            #pragma unroll
            for (int i = tid; i < 1024; i += NTHR) {
                int r = i >> 3, c = i & 7;
                CP_ASYNC16(sb + SMEM_A + (uint32_t)(r * 128 + ((c ^ (r & 7)) << 4)),
                           asrc + i);
            }
            const uint4* bs = (const uint4*)(g_bh + (size_t)t0 * BN * DDIM);
            #pragma unroll
            for (int i = tid; i < 512; i += NTHR) {
                int r = i >> 3, c = i & 7;
                CP_ASYNC16(sb + (uint32_t)(r * 128 + ((c ^ (r & 7)) << 4)), bs + i);
            }
            CP_COMMIT();
            const uint4* bs1 = (const uint4*)(g_bh + (size_t)(t0 + 1) * BN * DDIM);
            #pragma unroll
            for (int i = tid; i < 512; i += NTHR) {
                int r = i >> 3, c = i & 7;
                CP_ASYNC16(sb + 8192u + (uint32_t)(r * 128 + ((c ^ (r & 7)) << 4)), bs1 + i);
            }
            CP_COMMIT();
        }
        CP_WAIT(1);                         // A + B(t0) resident
        __syncthreads();

        uint32_t afr[2][4][4];
        #pragma unroll
        for (int mi = 0; mi < 2; mi++)
            #pragma unroll
            for (int ks = 0; ks < 4; ks++) {
                int m  = wm * 32 + mi * 16 + (g & 1) * 8 + r8;
                int kc = ks * 2 + (g >> 1);
                uint32_t addr = sb + SMEM_A + (uint32_t)(m * 128 + ((kc ^ (m & 7)) << 4));
                LDSM_X4(afr[mi][ks][0], afr[mi][ks][1], afr[mi][ks][2], afr[mi][ks][3], addr);
            }

        float s[4] = {0.f, 0.f, 0.f, 0.f};
        uint32_t hacc[4] = {0u, 0u, 0u, 0u};
        int cur = 0, nxt = 2;               // buf indices mod 3

        #pragma unroll 1
        for (int it = 0; it < CHUNK; it++) {
            const int t = t0 + it;
            // Wait for B(t): issued 2 iterations ago -> ~no-op in steady state.
            if (it == CHUNK - 1) { CP_WAIT(0); } else { CP_WAIT(1); }
            __syncthreads();                // all warps done with buf[nxt] reads

            if (it + 2 < CHUNK) {           // prefetch distance 2
                const uint32_t nbuf = sb + (uint32_t)(nxt << 13);
                const uint4* bs = (const uint4*)(g_bh + (size_t)(t + 2) * BN * DDIM);
                #pragma unroll
                for (int i = tid; i < 512; i += NTHR) {
                    int r = i >> 3, c = i & 7;
                    CP_ASYNC16(nbuf + (uint32_t)(r * 128 + ((c ^ (r & 7)) << 4)), bs + i);
                }
                CP_COMMIT();
            }
            const uint32_t bufb = sb + (uint32_t)(cur << 13);
            cur = (cur == 2) ? 0 : cur + 1;
            nxt = (nxt == 2) ? 0 : nxt + 1;

            // Accumulators pre-biased to -12: MMA yields logit-12 directly.
            uint32_t c_[2][4][2];
            #pragma unroll
            for (int mi = 0; mi < 2; mi++)
                #pragma unroll
                for (int ni = 0; ni < 4; ni++) {
                    c_[mi][ni][0] = BIAS_H2; c_[mi][ni][1] = BIAS_H2;
                }

            #pragma unroll
            for (int ks = 0; ks < 4; ks++) {
                uint32_t b[4][2];
                #pragma unroll
                for (int p = 0; p < 2; p++) {
                    uint32_t addr = bufb + brow[p] +
                                    (uint32_t)((((ks * 2 + kg) ^ bnlo[p])) << 4);
                    LDSM_X4(b[2 * p][0], b[2 * p][1], b[2 * p + 1][0], b[2 * p + 1][1], addr);
                }
                #pragma unroll
                for (int mi = 0; mi < 2; mi++)
                    #pragma unroll
                    for (int ni = 0; ni < 4; ni++)
                        MMA16816_F16(c_[mi][ni], afr[mi][ks], b[ni]);
            }

            // Diagonal capture: rows rb*128+[0,128) x cols t*64+[0,64)
            if ((t >> 1) == rb) {
                const int coff = (t & 1) << 6;
                #pragma unroll
                for (int mi = 0; mi < 2; mi++)
                    #pragma unroll
                    for (int ni = 0; ni < 4; ni++) {
                        float2 f0 = h2f(c_[mi][ni][0]);
                        float2 f1 = h2f(c_[mi][ni][1]);
                        int r0 = wm * 32 + mi * 16 + q, r1 = r0 + 8;
                        int cb = coff + wn * 32 + ni * 8 + 2 * p4;
                        if (r0 == cb)     g_pos[rb * BM + r0] = f0.x;
                        if (r0 == cb + 1) g_pos[rb * BM + r0] = f0.y;
                        if (r1 == cb)     g_pos[rb * BM + r1] = f1.x;
                        if (r1 == cb + 1) g_pos[rb * BM + r1] = f1.y;
                    }
            }

            // All-fp16 epilogue: ex2.f16x2 on raw MMA regs, HADD2 trees
            #pragma unroll
            for (int mi = 0; mi < 2; mi++)
                #pragma unroll
                for (int j = 0; j < 2; j++) {
                    uint32_t e0 = ex2_h2(c_[mi][0][j]);
                    uint32_t e1 = ex2_h2(c_[mi][1][j]);
                    uint32_t e2 = ex2_h2(c_[mi][2][j]);
                    uint32_t e3 = ex2_h2(c_[mi][3][j]);
                    uint32_t tsum = hadd2u(hadd2u(e0, e1), hadd2u(e2, e3));
                    hacc[mi * 2 + j] = hadd2u(hacc[mi * 2 + j], tsum);
                }
            if (it & 1) {                    // drain fp16 partials every 2 tiles
                #pragma unroll
                for (int slot = 0; slot < 4; slot++) {
                    float2 f = h2f(hacc[slot]);
                    s[slot] += f.x + f.y;
                    hacc[slot] = 0u;
                }
            }
        }

        // Per-chunk row-sum reduction — overlay on A stage (dead after afr).
        float* red = (float*)(smem + SMEM_A);   // [128][8]
        #pragma unroll
        for (int slot = 0; slot < 4; slot++) {
            int mi = slot >> 1, hi = slot & 1;
            int r = wm * 32 + mi * 16 + hi * 8 + q;
            red[r * 8 + wn * 4 + p4] = s[slot];
        }
        __syncthreads();
        if (tid < BM) {
            float tot = 0.f;
            #pragma unroll
            for (int i = 0; i < 8; i++) tot += red[tid * 8 + i];
            g_rowsum[ck * NROWS + rb * BM + tid] = tot;
        }
        // Loop-top sync (after ticket fetch) fences red/A reuse for next task.
    }
}

// ───────── Kernel 3: per-row LSE merge; last block does the final reduce ────
__global__ void finalize_kernel(float* __restrict__ out) {
    __shared__ float sh[256];
    int tid = threadIdx.x;
    int r = blockIdx.x * 256 + tid;
    float sum = 0.f;
    #pragma unroll
    for (int ck = 0; ck < NCHUNKS; ck++) sum += g_rowsum[ck * NROWS + r];
    // both sum and pos carry the 2^-12 / -12 bias -> cancels exactly
    sh[tid] = (log2f(sum) - g_pos[r]) * LN2F;
    __syncthreads();
    #pragma unroll
    for (int off = 128; off; off >>= 1) {
        if (tid < off) sh[tid] += sh[tid + off];
        __syncthreads();
    }
    int amLast = 0;
    if (tid == 0) {
        g_part1[blockIdx.x] = sh[0];
        __threadfence();
        amLast = (atomicAdd(&g_fin, 1u) == 63u);
    }
    amLast = __syncthreads_or(amLast);
    if (amLast) {
        if (tid == 0) g_fin = 0;           // reset for next graph replay
        if (tid < 64) sh[tid] = g_part1[tid];
        __syncthreads();
        if (tid == 0) {
            float tot = 0.f;
            #pragma unroll
            for (int i = 0; i < 64; i++) tot += sh[i];   // fixed order
            out[0] = tot * (1.0f / (float)NROWS);
        }
    }
}

// ────────────────────────────────────────────────────────────────────────────
extern "C" void kernel_launch(void* const* d_in, const int* in_sizes, int n_in,
                              void* d_out, int out_size) {
    const float* z1 = (const float*)d_in[0];
    const float* z2 = (const float*)d_in[1];
    float* out = (float*)d_out;

    normalize_kernel<<<2048, 256>>>(z1, z2);
    gemm_lse_kernel<<<GRID_P, NTHR>>>();
    finalize_kernel<<<64, 256>>>(out);
}

// round 12
// speedup vs baseline: 1.1022x; 1.1022x over previous
#include <cuda_runtime.h>
#include <cuda_fp16.h>
#include <cstdint>
#include <math.h>

#define NROWS 16384
#define DDIM  64
#define BM    128
#define BN    64
#define NTILES   (NROWS / BN)     // 256
#define CHUNK    16               // tiles per task
#define NPAIRS   (CHUNK / 2)      // 8
#define NCHUNKS  (NTILES / CHUNK) // 16 chunks per rowblock
#define NTASKS   ((NROWS / BM) * NCHUNKS)   // 2048
#define GRID_P   444
#define NTHR  256
#define SCALE_A 28.853900817779268f   // log2(e)/tau
#define LN2F    0.6931471805599453f
#define BIAS_H2 0xCA00CA00u           // packed half2(-12, -12)
#define SMEM_A  32768                 // A stage / reduction overlay

__device__ __half g_ah[NROWS * DDIM];      // z1n * log2(e)/tau  [m][k]
__device__ __half g_bh[NROWS * DDIM];      // z2n               [n][k]
__device__ float  g_rowsum[NCHUNKS * NROWS];   // biased by 2^-12 (cancels)
__device__ float  g_pos[NROWS];                // biased logit (cancels)
__device__ float  g_part1[64];
__device__ unsigned g_task = 0;            // dynamic ticket (reset by normalize)
__device__ unsigned g_fin  = 0;            // finalize last-block counter

__device__ __forceinline__ uint32_t smem_u32(const void* p) {
    uint32_t a;
    asm("{ .reg .u64 t; cvta.to.shared.u64 t, %1; cvt.u32.u64 %0, t; }" : "=r"(a) : "l"(p));
    return a;
}
__device__ __forceinline__ uint32_t ex2_h2(uint32_t x) {
    uint32_t r; asm("ex2.approx.f16x2 %0, %1;" : "=r"(r) : "r"(x)); return r;
}
__device__ __forceinline__ uint32_t hadd2u(uint32_t a, uint32_t b) {
    uint32_t r; asm("add.rn.f16x2 %0, %1, %2;" : "=r"(r) : "r"(a), "r"(b)); return r;
}
__device__ __forceinline__ float2 h2f(uint32_t u) {
    __half2 h = *reinterpret_cast<__half2*>(&u);
    return __half22float2(h);
}
#define LDSM_X4(r0, r1, r2, r3, addr) \
    asm volatile("ldmatrix.sync.aligned.m8n8.x4.shared.b16 {%0,%1,%2,%3}, [%4];" \
        : "=r"(r0), "=r"(r1), "=r"(r2), "=r"(r3) : "r"(addr))
#define MMA16816_F16(d, a, b) \
    asm volatile("mma.sync.aligned.m16n8k16.row.col.f16.f16.f16.f16 " \
        "{%0,%1}, {%2,%3,%4,%5}, {%6,%7}, {%0,%1};" \
        : "+r"((d)[0]), "+r"((d)[1]) \
        : "r"((a)[0]), "r"((a)[1]), "r"((a)[2]), "r"((a)[3]), "r"((b)[0]), "r"((b)[1]))
#define CP_ASYNC16(dst, src) \
    asm volatile("cp.async.cg.shared.global [%0], [%1], 16;" :: "r"(dst), "l"(src))
#define CP_COMMIT()  asm volatile("cp.async.commit_group;" ::: "memory")
#define CP_WAIT(n)   asm volatile("cp.async.wait_group %0;" :: "n"(n) : "memory")

// ─────────────── Kernel 1: L2-normalize + fp16 quantize + scale fold ────────
__global__ void normalize_kernel(const float* __restrict__ z1,
                                 const float* __restrict__ z2) {
    if (blockIdx.x == 0 && threadIdx.x == 0) g_task = 0;   // reset ticket

    int warp = blockIdx.x * (blockDim.x >> 5) + (threadIdx.x >> 5);
    int lane = threadIdx.x & 31;
    int row  = warp * 2 + (lane >> 4);
    int l16  = lane & 15;

    const float* src; __half* dst; float scale; int r;
    if (row < NROWS) { src = z1; dst = g_ah; r = row;          scale = SCALE_A; }
    else             { src = z2; dst = g_bh; r = row - NROWS;  scale = 1.0f;    }

    float4 v = ((const float4*)(src + (size_t)r * DDIM))[l16];
    float ss = v.x * v.x + v.y * v.y + v.z * v.z + v.w * v.w;
    #pragma unroll
    for (int off = 8; off; off >>= 1)
        ss += __shfl_xor_sync(0xffffffffu, ss, off);
    float inv = scale / fmaxf(sqrtf(ss), 1e-12f);
    __half2 h0 = __floats2half2_rn(v.x * inv, v.y * inv);
    __half2 h1 = __floats2half2_rn(v.z * inv, v.w * inv);
    uint2 o = make_uint2(*(uint32_t*)&h0, *(uint32_t*)&h1);
    ((uint2*)(dst + (size_t)r * DDIM))[l16] = o;
}

// ── Kernel 2: persistent fp16 GEMM, 2 tiles per barrier, 3 CTAs/SM ─────────
// smem: B pair0 [0,16K), B pair1 [16K,32K), A stage [32K,48K)
__global__ void __launch_bounds__(NTHR, 3) gemm_lse_kernel() {
    __shared__ __align__(128) char smem[49152];
    __shared__ int s_task;
    const uint32_t sb = smem_u32(smem);
    const int tid = threadIdx.x, lane = tid & 31, w = tid >> 5;
    const int wm = w >> 1, wn = w & 1;          // 4x2 warp grid, 32x32 tiles
    const int g = lane >> 3, r8 = lane & 7;
    const int kg = g & 1;
    const int q = lane >> 2, p4 = lane & 3;

    uint32_t brow[2]; int bnlo[2];
    #pragma unroll
    for (int p = 0; p < 2; p++) {
        int n = wn * 32 + p * 16 + (g >> 1) * 8 + r8;
        brow[p] = (uint32_t)(n * 128);
        bnlo[p] = n & 7;
    }

    for (;;) {
        if (tid == 0) s_task = (int)atomicAdd(&g_task, 1u);
        __syncthreads();
        const int task = s_task;
        if (task >= NTASKS) break;
        const int rb = task >> 4, ck = task & 15, t0 = ck << 4;

        // Preamble: A + B pair0 (tiles t0, t0+1), one group, wait once.
        {
            const uint4* asrc = (const uint4*)(g_ah + (size_t)rb * BM * DDIM);
            #pragma unroll
            for (int i = tid; i < 1024; i += NTHR) {
                int r = i >> 3, c = i & 7;
                CP_ASYNC16(sb + SMEM_A + (uint32_t)(r * 128 + ((c ^ (r & 7)) << 4)),
                           asrc + i);
            }
            const uint4* bs = (const uint4*)(g_bh + (size_t)t0 * BN * DDIM);
            #pragma unroll
            for (int i = tid; i < 1024; i += NTHR) {    // 2 tiles = 1024 uint4
                int r = i >> 3, c = i & 7;              // r in [0,128): 2 tiles
                CP_ASYNC16(sb + (uint32_t)(((r >> 6) << 13) + (r & 63) * 128
                                           + ((c ^ (r & 7)) << 4)), bs + i);
            }
            CP_COMMIT();
        }
        CP_WAIT(0);
        __syncthreads();

        uint32_t afr[2][4][4];
        #pragma unroll
        for (int mi = 0; mi < 2; mi++)
            #pragma unroll
            for (int ks = 0; ks < 4; ks++) {
                int m  = wm * 32 + mi * 16 + (g & 1) * 8 + r8;
                int kc = ks * 2 + (g >> 1);
                uint32_t addr = sb + SMEM_A + (uint32_t)(m * 128 + ((kc ^ (m & 7)) << 4));
                LDSM_X4(afr[mi][ks][0], afr[mi][ks][1], afr[mi][ks][2], afr[mi][ks][3], addr);
            }

        float s[4] = {0.f, 0.f, 0.f, 0.f};
        uint32_t hacc[4] = {0u, 0u, 0u, 0u};

        #pragma unroll 1
        for (int j = 0; j < NPAIRS; j++) {
            const int t = t0 + 2 * j;
            const uint32_t pbase = sb + (uint32_t)((j & 1) << 14);
            // Prefetch next pair into the other pair-buffer. Safe: that pair
            // was last READ in iteration j-1, fenced by the end-of-j-1 sync.
            if (j < NPAIRS - 1) {
                const uint32_t nbase = sb + (uint32_t)(((j + 1) & 1) << 14);
                const uint4* bs = (const uint4*)(g_bh + (size_t)(t + 2) * BN * DDIM);
                #pragma unroll
                for (int i = tid; i < 1024; i += NTHR) {
                    int r = i >> 3, c = i & 7;
                    CP_ASYNC16(nbase + (uint32_t)(((r >> 6) << 13) + (r & 63) * 128
                                                  + ((c ^ (r & 7)) << 4)), bs + i);
                }
                CP_COMMIT();
            }

            // ── Two tiles, no barrier in between ──
            #pragma unroll
            for (int half = 0; half < 2; half++) {
                const int tt = t + half;
                const uint32_t bufb = pbase + (uint32_t)(half << 13);

                // Accumulators pre-biased to -12: MMA yields logit-12 directly.
                uint32_t c_[2][4][2];
                #pragma unroll
                for (int mi = 0; mi < 2; mi++)
                    #pragma unroll
                    for (int ni = 0; ni < 4; ni++) {
                        c_[mi][ni][0] = BIAS_H2; c_[mi][ni][1] = BIAS_H2;
                    }

                #pragma unroll
                for (int ks = 0; ks < 4; ks++) {
                    uint32_t b[4][2];
                    #pragma unroll
                    for (int p = 0; p < 2; p++) {
                        uint32_t addr = bufb + brow[p] +
                                        (uint32_t)((((ks * 2 + kg) ^ bnlo[p])) << 4);
                        LDSM_X4(b[2 * p][0], b[2 * p][1], b[2 * p + 1][0], b[2 * p + 1][1], addr);
                    }
                    #pragma unroll
                    for (int mi = 0; mi < 2; mi++)
                        #pragma unroll
                        for (int ni = 0; ni < 4; ni++)
                            MMA16816_F16(c_[mi][ni], afr[mi][ks], b[ni]);
                }

                // Diagonal capture: rows rb*128+[0,128) x cols tt*64+[0,64)
                if ((tt >> 1) == rb) {
                    const int coff = (tt & 1) << 6;
                    #pragma unroll
                    for (int mi = 0; mi < 2; mi++)
                        #pragma unroll
                        for (int ni = 0; ni < 4; ni++) {
                            float2 f0 = h2f(c_[mi][ni][0]);
                            float2 f1 = h2f(c_[mi][ni][1]);
                            int r0 = wm * 32 + mi * 16 + q, r1 = r0 + 8;
                            int cb = coff + wn * 32 + ni * 8 + 2 * p4;
                            if (r0 == cb)     g_pos[rb * BM + r0] = f0.x;
                            if (r0 == cb + 1) g_pos[rb * BM + r0] = f0.y;
                            if (r1 == cb)     g_pos[rb * BM + r1] = f1.x;
                            if (r1 == cb + 1) g_pos[rb * BM + r1] = f1.y;
                        }
                }

                // All-fp16 epilogue: ex2.f16x2 on raw MMA regs, HADD2 trees
                #pragma unroll
                for (int mi = 0; mi < 2; mi++)
                    #pragma unroll
                    for (int jj = 0; jj < 2; jj++) {
                        uint32_t e0 = ex2_h2(c_[mi][0][jj]);
                        uint32_t e1 = ex2_h2(c_[mi][1][jj]);
                        uint32_t e2 = ex2_h2(c_[mi][2][jj]);
                        uint32_t e3 = ex2_h2(c_[mi][3][jj]);
                        uint32_t tsum = hadd2u(hadd2u(e0, e1), hadd2u(e2, e3));
                        hacc[mi * 2 + jj] = hadd2u(hacc[mi * 2 + jj], tsum);
                    }
            }

            // Drain fp16 partials once per pair
            #pragma unroll
            for (int slot = 0; slot < 4; slot++) {
                float2 f = h2f(hacc[slot]);
                s[slot] += f.x + f.y;
                hacc[slot] = 0u;
            }

            if (j < NPAIRS - 1) {
                CP_WAIT(0);                 // next pair resident
                __syncthreads();            // + all warps done reading pbase
            }
        }

        // Per-chunk row-sum reduction — overlay on A stage (dead after afr).
        __syncthreads();                    // all warps done with last pair
        float* red = (float*)(smem + SMEM_A);   // [128][8]
        #pragma unroll
        for (int slot = 0; slot < 4; slot++) {
            int mi = slot >> 1, hi = slot & 1;
            int r = wm * 32 + mi * 16 + hi * 8 + q;
            red[r * 8 + wn * 4 + p4] = s[slot];
        }
        __syncthreads();
        if (tid < BM) {
            float tot = 0.f;
            #pragma unroll
            for (int i = 0; i < 8; i++) tot += red[tid * 8 + i];
            g_rowsum[ck * NROWS + rb * BM + tid] = tot;
        }
        // Loop-top sync (after ticket fetch) fences red/A reuse for next task.
    }
}

// ───────── Kernel 3: per-row LSE merge; last block does the final reduce ────
__global__ void finalize_kernel(float* __restrict__ out) {
    __shared__ float sh[256];
    int tid = threadIdx.x;
    int r = blockIdx.x * 256 + tid;
    float sum = 0.f;
    #pragma unroll
    for (int ck = 0; ck < NCHUNKS; ck++) sum += g_rowsum[ck * NROWS + r];
    // both sum and pos carry the 2^-12 / -12 bias -> cancels exactly
    sh[tid] = (log2f(sum) - g_pos[r]) * LN2F;
    __syncthreads();
    #pragma unroll
    for (int off = 128; off; off >>= 1) {
        if (tid < off) sh[tid] += sh[tid + off];
        __syncthreads();
    }
    int amLast = 0;
    if (tid == 0) {
        g_part1[blockIdx.x] = sh[0];
        __threadfence();
        amLast = (atomicAdd(&g_fin, 1u) == 63u);
    }
    amLast = __syncthreads_or(amLast);
    if (amLast) {
        if (tid == 0) g_fin = 0;           // reset for next graph replay
        if (tid < 64) sh[tid] = g_part1[tid];
        __syncthreads();
        if (tid == 0) {
            float tot = 0.f;
            #pragma unroll
            for (int i = 0; i < 64; i++) tot += sh[i];   // fixed order
            out[0] = tot * (1.0f / (float)NROWS);
        }
    }
}

// ────────────────────────────────────────────────────────────────────────────
extern "C" void kernel_launch(void* const* d_in, const int* in_sizes, int n_in,
                              void* d_out, int out_size) {
    const float* z1 = (const float*)d_in[0];
    const float* z2 = (const float*)d_in[1];
    float* out = (float*)d_out;

    normalize_kernel<<<2048, 256>>>(z1, z2);
    gemm_lse_kernel<<<GRID_P, NTHR>>>();
    finalize_kernel<<<64, 256>>>(out);
}